// round 5
// baseline (speedup 1.0000x reference)
#include <cuda_runtime.h>

#define TT 100
#define BB 32768

// Dot product emulating LLVM/NEON k-vectorized reduction:
//   4 strided lanes: lane_j += w[4i+j] * v[4i+j]   (fmla, sequential over i)
//   horizontal reduce via faddp pairs: (l0+l1) + (l2+l3)
//   scalar fma tail for K % 4 elements
template <int K>
__device__ __forceinline__ float dot_vec4(const float* __restrict__ w,
                                          const float* __restrict__ v)
{
    constexpr int NV = K / 4;
    float l0 = 0.0f, l1 = 0.0f, l2 = 0.0f, l3 = 0.0f;
    #pragma unroll
    for (int i = 0; i < NV; i++) {
        l0 = fmaf(w[4 * i + 0], v[4 * i + 0], l0);
        l1 = fmaf(w[4 * i + 1], v[4 * i + 1], l1);
        l2 = fmaf(w[4 * i + 2], v[4 * i + 2], l2);
        l3 = fmaf(w[4 * i + 3], v[4 * i + 3], l3);
    }
    float s = __fadd_rn(__fadd_rn(l0, l1), __fadd_rn(l2, l3));
    #pragma unroll
    for (int i = 4 * NV; i < K; i++) s = fmaf(w[i], v[i], s);
    return s;
}

__global__ __launch_bounds__(32) void snn_kernel(
    const float* __restrict__ x,
    const float* __restrict__ w_s1, const float* __restrict__ b_s1,
    const float* __restrict__ w_s2, const float* __restrict__ b_s2,
    const float* __restrict__ w_c1, const float* __restrict__ b_c1,
    const float* __restrict__ w_co, const float* __restrict__ b_co,
    const float* __restrict__ w_ro, const float* __restrict__ b_ro,
    float* __restrict__ out)
{
    __shared__ float s_ws1[28 * 32];
    __shared__ float s_bs1[28];
    __shared__ float s_ws2[14 * 28];
    __shared__ float s_bs2[14];
    __shared__ float s_wc1[8 * 14];
    __shared__ float s_bc1[8];
    __shared__ float s_wco[3 * 8];
    __shared__ float s_bco[3];
    __shared__ float s_wro[14];
    __shared__ float s_bro[1];

    const int tid = threadIdx.x;
    for (int i = tid; i < 28 * 32; i += 32) s_ws1[i] = w_s1[i];
    for (int i = tid; i < 28;      i += 32) s_bs1[i] = b_s1[i];
    for (int i = tid; i < 14 * 28; i += 32) s_ws2[i] = w_s2[i];
    for (int i = tid; i < 14;      i += 32) s_bs2[i] = b_s2[i];
    for (int i = tid; i < 8 * 14;  i += 32) s_wc1[i] = w_c1[i];
    for (int i = tid; i < 8;       i += 32) s_bc1[i] = b_c1[i];
    for (int i = tid; i < 3 * 8;   i += 32) s_wco[i] = w_co[i];
    for (int i = tid; i < 3;       i += 32) s_bco[i] = b_co[i];
    for (int i = tid; i < 14;      i += 32) s_wro[i] = w_ro[i];
    if (tid == 0) s_bro[0] = b_ro[0];
    __syncthreads();

    const int b = blockIdx.x * 32 + tid;

    float m1[28], m2[14], mc1[8], mco[3], mro;
    #pragma unroll
    for (int j = 0; j < 28; j++) m1[j] = 0.0f;
    #pragma unroll
    for (int j = 0; j < 14; j++) m2[j] = 0.0f;
    #pragma unroll
    for (int j = 0; j < 8; j++) mc1[j] = 0.0f;
    #pragma unroll
    for (int j = 0; j < 3; j++) mco[j] = 0.0f;
    mro = 0.0f;

    float* o_mco   = out;                          // (T,B,3)
    float* o_spkc1 = out + (size_t)TT * BB * 3;    // (T,B,8)
    float* o_mro   = out + (size_t)TT * BB * 11;   // (T,B,1)
    float* o_spk1  = out + (size_t)TT * BB * 12;   // (T,B,28)
    float* o_spk2  = out + (size_t)TT * BB * 40;   // (T,B,14)

    for (int t = 0; t < TT; t++) {
        const size_t base = (size_t)t * BB + b;

        // ---- load x_t[b][0:32] (contiguous 128B, 8x float4) ----
        float xv[32];
        const float4* xt = (const float4*)(x + base * 32);
        #pragma unroll
        for (int i = 0; i < 8; i++) {
            float4 v = xt[i];
            xv[4 * i + 0] = v.x; xv[4 * i + 1] = v.y;
            xv[4 * i + 2] = v.z; xv[4 * i + 3] = v.w;
        }

        // Arithmetic model:
        //   dot    = 4-lane strided fma lanes, faddp pairwise reduce, fma tail
        //   cur    = dot + bias              (separate rounded add)
        //   newmem = fmaf(0.9, mem, cur) - reset

        // ---- layer s1: 32 -> 28 ----
        float spk1[28];
        #pragma unroll
        for (int j = 0; j < 28; j++) {
            float cur = __fadd_rn(dot_vec4<32>(&s_ws1[j * 32], xv), s_bs1[j]);
            float rst = (m1[j] > 1.0f) ? 1.0f : 0.0f;   // reset uses PREVIOUS mem
            float nm  = __fadd_rn(fmaf(0.9f, m1[j], cur), -rst);
            m1[j]   = nm;
            spk1[j] = (nm > 1.0f) ? 1.0f : 0.0f;
        }

        // ---- layer s2: 28 -> 14 ----
        float spk2[14];
        #pragma unroll
        for (int j = 0; j < 14; j++) {
            float cur = __fadd_rn(dot_vec4<28>(&s_ws2[j * 28], spk1), s_bs2[j]);
            float rst = (m2[j] > 1.0f) ? 1.0f : 0.0f;
            float nm  = __fadd_rn(fmaf(0.9f, m2[j], cur), -rst);
            m2[j]   = nm;
            spk2[j] = (nm > 1.0f) ? 1.0f : 0.0f;
        }

        // ---- layer c1: 14 -> 8 ----
        float spkc1[8];
        #pragma unroll
        for (int j = 0; j < 8; j++) {
            float cur = __fadd_rn(dot_vec4<14>(&s_wc1[j * 14], spk2), s_bc1[j]);
            float rst = (mc1[j] > 1.0f) ? 1.0f : 0.0f;
            float nm  = __fadd_rn(fmaf(0.9f, mc1[j], cur), -rst);
            mc1[j]   = nm;
            spkc1[j] = (nm > 1.0f) ? 1.0f : 0.0f;
        }

        // ---- layer co: 8 -> 3 (only mem recorded) ----
        #pragma unroll
        for (int j = 0; j < 3; j++) {
            float cur = __fadd_rn(dot_vec4<8>(&s_wco[j * 8], spkc1), s_bco[j]);
            float rst = (mco[j] > 1.0f) ? 1.0f : 0.0f;
            mco[j] = __fadd_rn(fmaf(0.9f, mco[j], cur), -rst);
        }

        // ---- layer ro: 14 -> 1 (only mem recorded) ----
        {
            float cur = __fadd_rn(dot_vec4<14>(s_wro, spk2), s_bro[0]);
            float rst = (mro > 1.0f) ? 1.0f : 0.0f;
            mro = __fadd_rn(fmaf(0.9f, mro, cur), -rst);
        }

        // ---- stores (vectorized, coalesced per-warp contiguous regions) ----
        {
            float* p = o_mco + base * 3;
            p[0] = mco[0]; p[1] = mco[1]; p[2] = mco[2];
        }
        {
            float4* q = (float4*)(o_spkc1 + base * 8);
            q[0] = make_float4(spkc1[0], spkc1[1], spkc1[2], spkc1[3]);
            q[1] = make_float4(spkc1[4], spkc1[5], spkc1[6], spkc1[7]);
        }
        o_mro[base] = mro;
        {
            float4* r = (float4*)(o_spk1 + base * 28);
            #pragma unroll
            for (int j = 0; j < 7; j++)
                r[j] = make_float4(spk1[4 * j], spk1[4 * j + 1],
                                   spk1[4 * j + 2], spk1[4 * j + 3]);
        }
        {
            float2* s2 = (float2*)(o_spk2 + base * 14);
            #pragma unroll
            for (int j = 0; j < 7; j++)
                s2[j] = make_float2(spk2[2 * j], spk2[2 * j + 1]);
        }
    }
}

extern "C" void kernel_launch(void* const* d_in, const int* in_sizes, int n_in,
                              void* d_out, int out_size) {
    snn_kernel<<<BB / 32, 32>>>(
        (const float*)d_in[0],
        (const float*)d_in[1],  (const float*)d_in[2],
        (const float*)d_in[3],  (const float*)d_in[4],
        (const float*)d_in[5],  (const float*)d_in[6],
        (const float*)d_in[7],  (const float*)d_in[8],
        (const float*)d_in[9],  (const float*)d_in[10],
        (float*)d_out);
}